// round 6
// baseline (speedup 1.0000x reference)
#include <cuda_runtime.h>
#include <stdint.h>
#include <math.h>

#define BS   8
#define CCH  256
#define NND  9216     // H*W
#define EED  9215     // N-1 edges
#define ZETA 0.01f

#define CPB  16               // channels per dist block
#define GQ   (CCH/CPB)        // 16 groups per batch
#define TCH  2                // channels per tile step
#define NSTEP (CPB/TCH)       // 8 tile steps
#define MAXD 511
#define NT   1024
#define EPT  9                // ceil(EED/NT)
#define NCHUNK (NND/NT)       // 9
#define GRID (BS + BS*GQ)     // 8 scan blocks + 128 dist blocks = 136

// scratch (static device globals — no allocations)
__device__ float g_part[(size_t)BS * GQ * EED];
__device__ float g_wgt[(size_t)BS * EED];
__device__ int   g_done[BS];
__device__ int   g_flag[BS];

extern __shared__ float dyn_smem[];

__device__ __forceinline__ void cp_async16(uint32_t saddr, const void* gptr) {
    asm volatile("cp.async.cg.shared.global [%0], [%1], 16;\n"
                 :: "r"(saddr), "l"(gptr));
}
__device__ __forceinline__ void cp_commit() {
    asm volatile("cp.async.commit_group;\n");
}
template <int N>
__device__ __forceinline__ void cp_wait() {
    asm volatile("cp.async.wait_group %0;\n" :: "n"(N));
}

// ---------------------------------------------------------------------------
__global__ void init_kernel() {
    if (threadIdx.x < BS) { g_done[threadIdx.x] = 0; g_flag[threadIdx.x] = 0; }
}

// ---------------------------------------------------------------------------
// Dist role: blocks 8..135. One block per (batch, 16-channel group), double-
// buffered cp.async tiles. The 16th finisher per batch reduces partials and
// computes weights (fixed summation order -> deterministic), then releases
// the per-batch flag.
// ---------------------------------------------------------------------------
__device__ void dist_role(const float* __restrict__ emb,
                          const int*   __restrict__ tree,
                          int id) {
    float* buf0 = dyn_smem;
    float* buf1 = dyn_smem + TCH * NND;
    const int b   = id / GQ;
    const int g   = id % GQ;
    const int tid = threadIdx.x;

    const float* base = emb + ((size_t)b * CCH + (size_t)g * CPB) * NND;
    uint32_t s0 = (uint32_t)__cvta_generic_to_shared(buf0);
    uint32_t s1 = (uint32_t)__cvta_generic_to_shared(buf1);
    const int WORDS = TCH * NND / 4;

    for (int i = tid; i < WORDS; i += NT)
        cp_async16(s0 + i * 16, base + i * 4);
    cp_commit();

    const int2* tr2 = (const int2*)(tree + (size_t)b * EED * 2);
    int2 ed[EPT];
    float acc[EPT];
#pragma unroll
    for (int k = 0; k < EPT; k++) {
        int e = tid + k * NT;
        ed[k]  = (e < EED) ? tr2[e] : make_int2(0, 0);
        acc[k] = 0.f;
    }

    for (int t = 0; t < NSTEP; t++) {
        if (t + 1 < NSTEP) {
            uint32_t dst = (t & 1) ? s0 : s1;
            const float* srcp = base + (size_t)(t + 1) * TCH * NND;
            for (int i = tid; i < WORDS; i += NT)
                cp_async16(dst + i * 16, srcp + i * 4);
            cp_commit();
            cp_wait<1>();
        } else {
            cp_wait<0>();
        }
        __syncthreads();
        const float* cur = (t & 1) ? buf1 : buf0;
#pragma unroll
        for (int k = 0; k < EPT; k++) {
            float a0 = cur[ed[k].x];
            float b0 = cur[ed[k].y];
            float a1 = cur[NND + ed[k].x];
            float b1 = cur[NND + ed[k].y];
            float d0 = a0 - b0, d1 = a1 - b1;
            acc[k] += d0 * d0 + d1 * d1;
        }
        __syncthreads();
    }

    float* outp = g_part + ((size_t)b * GQ + g) * EED;
#pragma unroll
    for (int k = 0; k < EPT; k++) {
        int e = tid + k * NT;
        if (e < EED) outp[e] = acc[k];
    }

    // release our partials, detect last finisher for this batch
    __threadfence();
    __syncthreads();
    __shared__ int s_last;
    if (tid == 0) s_last = (atomicAdd(&g_done[b], 1) == GQ - 1);
    __syncthreads();
    if (!s_last) return;

    // last finisher: reduce 16 partial rows + exp (deterministic order)
    const float* pp = g_part + (size_t)b * GQ * EED;
    float* wp = g_wgt + (size_t)b * EED;
#pragma unroll
    for (int k = 0; k < EPT; k++) {
        int e = tid + k * NT;
        if (e < EED) {
            float s = 0.f;
#pragma unroll
            for (int q = 0; q < GQ; q++)
                s += __ldcg(pp + (size_t)q * EED + e);
            wp[e] = __expf(-ZETA * s);
        }
    }
    __threadfence();
    __syncthreads();
    if (tid == 0) atomicExch(&g_flag[b], 1);
}

// ---------------------------------------------------------------------------
// Scan role: blocks 0..7 (one per batch). Prologue (tree-only) runs
// concurrently with dist; spin-waits on g_flag[b] before filling W and
// running the level-parallel passes.
// smem: region A = par/dep -> SZ float2[NND];  B = ST int2[EED];  C = W[EED]
// ---------------------------------------------------------------------------
__device__ void scan_role(const float* __restrict__ fin,
                          const int*   __restrict__ tree,
                          float*       __restrict__ out,
                          int b) {
    const int tid = threadIdx.x;
    const int wid = tid >> 5;
    const int lid = tid & 31;

    char*   smbase = (char*)dyn_smem;
    float2* SZ = (float2*)smbase;
    int2*   ST = (int2*)(smbase + (size_t)NND * 8);
    float*  W  = (float*)(smbase + (size_t)NND * 8 + (size_t)EED * 8);
    int*    par = (int*)smbase;
    int*    dep = par + NND;

    __shared__ int hist[MAXD + 1];
    __shared__ int lvlo[MAXD + 2];
    __shared__ int warpsum[16];
    __shared__ int s_maxLvl, s_bad;

    const int2* tr2 = (const int2*)(tree + (size_t)b * EED * 2);

    // ---- parent array + per-thread edge cache ----
    if (tid == 0) { s_maxLvl = 1; s_bad = 0; par[0] = 0; dep[0] = 0; }
    int2 ed[EPT];
#pragma unroll
    for (int k = 0; k < EPT; k++) {
        int e = tid + k * NT;
        ed[k] = (e < EED) ? tr2[e] : make_int2(0, 0);
        if (e < EED) par[ed[k].y] = ed[k].x;
    }
    __syncthreads();

    // ---- depth: chunked walk (parent index < child index) ----
#pragma unroll 1
    for (int c = 0; c < NCHUNK; c++) {
        int i = c * NT + tid;
        if (i > 0) {
            int B = c * NT;
            int j = par[i], d = 1;
            while (j >= B && j > 0) { j = par[j]; d++; }
            dep[i] = d + dep[j];
        }
        __syncthreads();
    }

    // ---- histogram of child depths (cached in regs) ----
    for (int k = tid; k <= MAXD; k += NT) hist[k] = 0;
    __syncthreads();
    int myd[EPT];
#pragma unroll
    for (int k = 0; k < EPT; k++) {
        int e = tid + k * NT;
        if (e < EED) {
            int d = dep[ed[k].y];
            myd[k] = d > MAXD ? MAXD : d;
            atomicAdd(&hist[myd[k]], 1);
        } else myd[k] = 0;
    }
    __syncthreads();

    // ---- 2-barrier block scan over 512 bins (warps 0..15) ----
    int binv = 0, incl = 0, bin = 0;
    if (wid < 16) {
        bin  = wid * 32 + lid;
        binv = hist[bin];
        int v = binv;
#pragma unroll
        for (int off = 1; off < 32; off <<= 1) {
            int t = __shfl_up_sync(0xffffffffu, v, off);
            if (lid >= off) v += t;
        }
        if (lid == 31) warpsum[wid] = v;
        incl = v;
    }
    __syncthreads();
    if (wid == 0 && lid < 16) {
        int v = warpsum[lid];
#pragma unroll
        for (int off = 1; off < 16; off <<= 1) {
            int t = __shfl_up_sync(0xffffu, v, off);
            if (lid >= off) v += t;
        }
        warpsum[lid] = v;
    }
    __syncthreads();
    if (wid < 16) {
        incl += wid ? warpsum[wid - 1] : 0;
        lvlo[bin + 1] = incl;
        hist[bin] = incl - binv;          // exclusive cursor for scatter
        if (binv > 0)  atomicMax(&s_maxLvl, bin);
        if (binv > 32) atomicMax(&s_bad, bin);
    }
    if (tid == 0) lvlo[0] = 0;
    __syncthreads();

    // ---- scatter (s,t) into level order; remember positions ----
    int pos[EPT];
#pragma unroll
    for (int k = 0; k < EPT; k++) {
        int e = tid + k * NT;
        if (e < EED) {
            pos[k] = atomicAdd(&hist[myd[k]], 1);
            ST[pos[k]] = ed[k];
        } else pos[k] = 0;
    }

    // ---- init SZ (overwrites par/dep region) ----
    __syncthreads();
    const float* fb = fin + (size_t)b * NND;
    for (int i = tid; i < NND; i += NT) SZ[i] = make_float2(fb[i], 1.f);

    // ---- wait for this batch's weights ----
    if (tid == 0) {
        while (atomicAdd(&g_flag[b], 0) == 0) __nanosleep(64);
        __threadfence();
    }
    __syncthreads();

    const float* wp = g_wgt + (size_t)b * EED;
#pragma unroll
    for (int k = 0; k < EPT; k++) {
        int e = tid + k * NT;
        if (e < EED) W[pos[k]] = __ldcg(wp + e);
    }
    __syncthreads();

    const int maxLvl = s_maxLvl;
    const int bad    = s_bad;        // deepest level with count > 32

    // ---- UP pass: tail (small deep levels) on warp 0 ----
    if (wid == 0) {
#pragma unroll 1
        for (int d = maxLvl; d > bad; --d) {
            int idx = lvlo[d] + lid;
            if (idx < lvlo[d + 1]) {
                int2 st = ST[idx];
                float w = W[idx];
                float2 v = SZ[st.y];
                atomicAdd(&SZ[st.x].x, w * v.x);
                atomicAdd(&SZ[st.x].y, w * v.y);
            }
            __syncwarp();
        }
    }
    __syncthreads();
#pragma unroll 1
    for (int d = bad; d >= 1; --d) {
        int end = lvlo[d + 1];
        for (int idx = lvlo[d] + tid; idx < end; idx += NT) {
            int2 st = ST[idx];
            float w = W[idx];
            float2 v = SZ[st.y];
            atomicAdd(&SZ[st.x].x, w * v.x);
            atomicAdd(&SZ[st.x].y, w * v.y);
        }
        __syncthreads();
    }

    // ---- DOWN pass ----
#pragma unroll 1
    for (int d = 1; d <= bad; ++d) {
        int end = lvlo[d + 1];
        for (int idx = lvlo[d] + tid; idx < end; idx += NT) {
            int2 st = ST[idx];
            float w = W[idx];
            float om = 1.f - w * w;
            float2 p = SZ[st.x];
            float2 v = SZ[st.y];
            SZ[st.y] = make_float2(w * p.x + om * v.x, w * p.y + om * v.y);
        }
        __syncthreads();
    }
    if (wid == 0) {
#pragma unroll 1
        for (int d = bad + 1; d <= maxLvl; ++d) {
            int idx = lvlo[d] + lid;
            if (idx < lvlo[d + 1]) {
                int2 st = ST[idx];
                float w = W[idx];
                float om = 1.f - w * w;
                float2 p = SZ[st.x];
                float2 v = SZ[st.y];
                SZ[st.y] = make_float2(w * p.x + om * v.x, w * p.y + om * v.y);
            }
            __syncwarp();
        }
    }
    __syncthreads();

    // ---- output = F/G ----
    float* ob = out + (size_t)b * NND;
    for (int i = tid; i < NND; i += NT) {
        float2 v = SZ[i];
        ob[i] = v.x / v.y;
    }
}

// ---------------------------------------------------------------------------
__global__ void __launch_bounds__(NT, 1)
fused_kernel(const float* __restrict__ fin,
             const float* __restrict__ emb,
             const int*   __restrict__ tree,
             float*       __restrict__ out) {
    if (blockIdx.x >= BS)
        dist_role(emb, tree, blockIdx.x - BS);
    else
        scan_role(fin, tree, out, blockIdx.x);
}

// ---------------------------------------------------------------------------
extern "C" void kernel_launch(void* const* d_in, const int* in_sizes, int n_in,
                              void* d_out, int out_size) {
    const float* f    = (const float*)d_in[0];   // feature_in [8,1,96,96]
    const float* emb  = (const float*)d_in[1];   // embed_in   [8,256,96,96]
    const int*   tree = (const int*)d_in[2];     // tree       [8,9215,2]
    float*       out  = (float*)d_out;           // [8,1,96,96]

    init_kernel<<<1, 32>>>();

    size_t smem = (size_t)NND * 8 + (size_t)EED * 8 + (size_t)EED * 4 + 16;
    cudaFuncSetAttribute(fused_kernel,
                         cudaFuncAttributeMaxDynamicSharedMemorySize,
                         (int)smem);
    fused_kernel<<<GRID, NT, smem>>>(f, emb, tree, out);
}

// round 7
// speedup vs baseline: 1.1394x; 1.1394x over previous
#include <cuda_runtime.h>
#include <stdint.h>
#include <math.h>

#define BS   8
#define CCH  256
#define NND  9216     // H*W
#define EED  9215     // N-1 edges
#define ZETA 0.01f

#define CPB  16               // channels per dist block
#define GQ   (CCH/CPB)        // 16 groups per batch
#define TCH  2                // channels per tile step
#define NSTEP (CPB/TCH)       // 8 tile steps
#define MAXD 511
#define NT   1024
#define EPT  9                // ceil(EED/NT)
#define NCHUNK (NND/NT)       // 9

// per-edge squared-distance accumulator; zero-init at load, re-zeroed by the
// scan kernel after use so every graph replay sees zeros.
__device__ float g_sum[(size_t)BS * EED];

extern __shared__ float dyn_smem[];

__device__ __forceinline__ void cp_async16(uint32_t saddr, const void* gptr) {
    asm volatile("cp.async.cg.shared.global [%0], [%1], 16;\n"
                 :: "r"(saddr), "l"(gptr));
}
__device__ __forceinline__ void cp_commit() {
    asm volatile("cp.async.commit_group;\n");
}
template <int N>
__device__ __forceinline__ void cp_wait() {
    asm volatile("cp.async.wait_group %0;\n" :: "n"(N));
}

// ---------------------------------------------------------------------------
// K1: partial squared distances. One block per (batch, 16-channel group),
// double-buffered cp.async tiles; per-edge partials reduced straight into
// g_sum via global float atomics (REDG) — no partial-matrix round trip.
// ---------------------------------------------------------------------------
__global__ void __launch_bounds__(NT, 1)
dist_kernel(const float* __restrict__ emb,
            const int*   __restrict__ tree) {
    float* buf0 = dyn_smem;
    float* buf1 = dyn_smem + TCH * NND;
    const int b   = blockIdx.x / GQ;
    const int g   = blockIdx.x % GQ;
    const int tid = threadIdx.x;

    const float* base = emb + ((size_t)b * CCH + (size_t)g * CPB) * NND;
    uint32_t s0 = (uint32_t)__cvta_generic_to_shared(buf0);
    uint32_t s1 = (uint32_t)__cvta_generic_to_shared(buf1);
    const int WORDS = TCH * NND / 4;

    for (int i = tid; i < WORDS; i += NT)
        cp_async16(s0 + i * 16, base + i * 4);
    cp_commit();

    const int2* tr2 = (const int2*)(tree + (size_t)b * EED * 2);
    int2 ed[EPT];
    float acc[EPT];
#pragma unroll
    for (int k = 0; k < EPT; k++) {
        int e = tid + k * NT;
        ed[k]  = (e < EED) ? tr2[e] : make_int2(0, 0);
        acc[k] = 0.f;
    }

    for (int t = 0; t < NSTEP; t++) {
        if (t + 1 < NSTEP) {
            uint32_t dst = (t & 1) ? s0 : s1;
            const float* srcp = base + (size_t)(t + 1) * TCH * NND;
            for (int i = tid; i < WORDS; i += NT)
                cp_async16(dst + i * 16, srcp + i * 4);
            cp_commit();
            cp_wait<1>();
        } else {
            cp_wait<0>();
        }
        __syncthreads();
        const float* cur = (t & 1) ? buf1 : buf0;
#pragma unroll
        for (int k = 0; k < EPT; k++) {
            float a0 = cur[ed[k].x];
            float b0 = cur[ed[k].y];
            float a1 = cur[NND + ed[k].x];
            float b1 = cur[NND + ed[k].y];
            float d0 = a0 - b0, d1 = a1 - b1;
            acc[k] += d0 * d0 + d1 * d1;
        }
        __syncthreads();
    }

    float* sp = g_sum + (size_t)b * EED;
#pragma unroll
    for (int k = 0; k < EPT; k++) {
        int e = tid + k * NT;
        if (e < EED) atomicAdd(sp + e, acc[k]);
    }
}

// ---------------------------------------------------------------------------
// K2: per-batch level-parallel tree scans. Weights computed inline from
// g_sum during the W fill; g_sum row re-zeroed immediately after (replay
// hygiene), overlapping the passes.
// smem: region A = par/dep -> SZ float2[NND];  B = ST int2[EED];  C = W[EED]
// ---------------------------------------------------------------------------
__global__ void __launch_bounds__(NT, 1)
scan_kernel(const float* __restrict__ fin,
            const int*   __restrict__ tree,
            float*       __restrict__ out) {
    const int b   = blockIdx.x;
    const int tid = threadIdx.x;
    const int wid = tid >> 5;
    const int lid = tid & 31;

    char*   smbase = (char*)dyn_smem;
    float2* SZ = (float2*)smbase;
    int2*   ST = (int2*)(smbase + (size_t)NND * 8);
    float*  W  = (float*)(smbase + (size_t)NND * 8 + (size_t)EED * 8);
    int*    par = (int*)smbase;
    int*    dep = par + NND;

    __shared__ int hist[MAXD + 1];
    __shared__ int lvlo[MAXD + 2];
    __shared__ int warpsum[16];
    __shared__ int s_maxLvl, s_bad;

    const int2* tr2 = (const int2*)(tree + (size_t)b * EED * 2);

    // ---- parent array + per-thread edge cache ----
    if (tid == 0) { s_maxLvl = 1; s_bad = 0; par[0] = 0; dep[0] = 0; }
    int2 ed[EPT];
#pragma unroll
    for (int k = 0; k < EPT; k++) {
        int e = tid + k * NT;
        ed[k] = (e < EED) ? tr2[e] : make_int2(0, 0);
        if (e < EED) par[ed[k].y] = ed[k].x;
    }
    __syncthreads();

    // ---- depth: chunked walk (parent index < child index) ----
#pragma unroll 1
    for (int c = 0; c < NCHUNK; c++) {
        int i = c * NT + tid;
        if (i > 0) {
            int B = c * NT;
            int j = par[i], d = 1;
            while (j >= B && j > 0) { j = par[j]; d++; }
            dep[i] = d + dep[j];
        }
        __syncthreads();
    }

    // ---- histogram of child depths (cached in regs) ----
    for (int k = tid; k <= MAXD; k += NT) hist[k] = 0;
    __syncthreads();
    int myd[EPT];
#pragma unroll
    for (int k = 0; k < EPT; k++) {
        int e = tid + k * NT;
        if (e < EED) {
            int d = dep[ed[k].y];
            myd[k] = d > MAXD ? MAXD : d;
            atomicAdd(&hist[myd[k]], 1);
        } else myd[k] = 0;
    }
    __syncthreads();

    // ---- 2-barrier block scan over 512 bins (warps 0..15) ----
    int binv = 0, incl = 0, bin = 0;
    if (wid < 16) {
        bin  = wid * 32 + lid;
        binv = hist[bin];
        int v = binv;
#pragma unroll
        for (int off = 1; off < 32; off <<= 1) {
            int t = __shfl_up_sync(0xffffffffu, v, off);
            if (lid >= off) v += t;
        }
        if (lid == 31) warpsum[wid] = v;
        incl = v;
    }
    __syncthreads();
    if (wid == 0 && lid < 16) {
        int v = warpsum[lid];
#pragma unroll
        for (int off = 1; off < 16; off <<= 1) {
            int t = __shfl_up_sync(0xffffu, v, off);
            if (lid >= off) v += t;
        }
        warpsum[lid] = v;
    }
    __syncthreads();
    if (wid < 16) {
        incl += wid ? warpsum[wid - 1] : 0;
        lvlo[bin + 1] = incl;
        hist[bin] = incl - binv;          // exclusive cursor for scatter
        if (binv > 0)  atomicMax(&s_maxLvl, bin);
        if (binv > 32) atomicMax(&s_bad, bin);
    }
    if (tid == 0) lvlo[0] = 0;
    __syncthreads();

    // ---- scatter (s,t) into level order; weights inline from g_sum ----
    float* sp = g_sum + (size_t)b * EED;
#pragma unroll
    for (int k = 0; k < EPT; k++) {
        int e = tid + k * NT;
        if (e < EED) {
            float w = __expf(-ZETA * __ldcg(sp + e));
            int pos = atomicAdd(&hist[myd[k]], 1);
            ST[pos] = ed[k];
            W[pos]  = w;
        }
    }

    // ---- re-zero g_sum row for the next replay (overlaps passes) ----
    for (int e = tid; e < EED; e += NT) sp[e] = 0.f;

    // ---- init SZ (overwrites par/dep region) ----
    __syncthreads();
    const float* fb = fin + (size_t)b * NND;
    for (int i = tid; i < NND; i += NT) SZ[i] = make_float2(fb[i], 1.f);
    __syncthreads();

    const int maxLvl = s_maxLvl;
    const int bad    = s_bad;        // deepest level with count > 32

    // ---- UP pass: tail (small deep levels) on warp 0 ----
    if (wid == 0) {
#pragma unroll 1
        for (int d = maxLvl; d > bad; --d) {
            int idx = lvlo[d] + lid;
            if (idx < lvlo[d + 1]) {
                int2 st = ST[idx];
                float w = W[idx];
                float2 v = SZ[st.y];
                atomicAdd(&SZ[st.x].x, w * v.x);
                atomicAdd(&SZ[st.x].y, w * v.y);
            }
            __syncwarp();
        }
    }
    __syncthreads();
#pragma unroll 1
    for (int d = bad; d >= 1; --d) {
        int end = lvlo[d + 1];
        for (int idx = lvlo[d] + tid; idx < end; idx += NT) {
            int2 st = ST[idx];
            float w = W[idx];
            float2 v = SZ[st.y];
            atomicAdd(&SZ[st.x].x, w * v.x);
            atomicAdd(&SZ[st.x].y, w * v.y);
        }
        __syncthreads();
    }

    // ---- DOWN pass ----
#pragma unroll 1
    for (int d = 1; d <= bad; ++d) {
        int end = lvlo[d + 1];
        for (int idx = lvlo[d] + tid; idx < end; idx += NT) {
            int2 st = ST[idx];
            float w = W[idx];
            float om = 1.f - w * w;
            float2 p = SZ[st.x];
            float2 v = SZ[st.y];
            SZ[st.y] = make_float2(w * p.x + om * v.x, w * p.y + om * v.y);
        }
        __syncthreads();
    }
    if (wid == 0) {
#pragma unroll 1
        for (int d = bad + 1; d <= maxLvl; ++d) {
            int idx = lvlo[d] + lid;
            if (idx < lvlo[d + 1]) {
                int2 st = ST[idx];
                float w = W[idx];
                float om = 1.f - w * w;
                float2 p = SZ[st.x];
                float2 v = SZ[st.y];
                SZ[st.y] = make_float2(w * p.x + om * v.x, w * p.y + om * v.y);
            }
            __syncwarp();
        }
    }
    __syncthreads();

    // ---- output = F/G ----
    float* ob = out + (size_t)b * NND;
    for (int i = tid; i < NND; i += NT) {
        float2 v = SZ[i];
        ob[i] = v.x / v.y;
    }
}

// ---------------------------------------------------------------------------
extern "C" void kernel_launch(void* const* d_in, const int* in_sizes, int n_in,
                              void* d_out, int out_size) {
    const float* f    = (const float*)d_in[0];   // feature_in [8,1,96,96]
    const float* emb  = (const float*)d_in[1];   // embed_in   [8,256,96,96]
    const int*   tree = (const int*)d_in[2];     // tree       [8,9215,2]
    float*       out  = (float*)d_out;           // [8,1,96,96]

    size_t smem_dist = 2 * (size_t)TCH * NND * sizeof(float);   // 147456 B
    cudaFuncSetAttribute(dist_kernel,
                         cudaFuncAttributeMaxDynamicSharedMemorySize,
                         (int)smem_dist);
    dist_kernel<<<BS * GQ, NT, smem_dist>>>(emb, tree);

    size_t smem_scan = (size_t)NND * 8 + (size_t)EED * 8 + (size_t)EED * 4;
    cudaFuncSetAttribute(scan_kernel,
                         cudaFuncAttributeMaxDynamicSharedMemorySize,
                         (int)smem_scan);
    scan_kernel<<<BS, NT, smem_scan>>>(f, tree, out);
}

// round 8
// speedup vs baseline: 1.1828x; 1.0381x over previous
#include <cuda_runtime.h>
#include <stdint.h>
#include <math.h>

#define BS   8
#define CCH  256
#define NND  9216     // H*W
#define EED  9215     // N-1 edges
#define EEDP 9216     // padded
#define ZETA 0.01f

#define CPB  16               // channels per dist block
#define GQ   (CCH/CPB)        // 16 groups per batch
#define TCH  2                // channels per tile step
#define NSTEP (CPB/TCH)       // 8 tile steps
#define MAXD 511
#define NT   1024
#define EPT  9                // ceil(EED/NT)
#define NCHUNK (NND/NT)       // 9
#define GRID1 (BS*GQ + BS)    // 128 dist + 8 prologue = 136

// static device scratch (zero-init at load; g_sum re-zeroed each run)
__device__ float g_sum[(size_t)BS * EED];        // per-edge squared dist
__device__ int2  g_ST[(size_t)BS * EEDP];        // level-sorted (s,t)
__device__ int   g_lvlo[BS][MAXD + 2];
__device__ int2  g_meta[BS];                     // (maxLvl, bad)
__device__ float g_FZ[2][(size_t)BS * NND];      // F and Z fields

extern __shared__ float dyn_smem[];

__device__ __forceinline__ void cp_async16(uint32_t saddr, const void* gptr) {
    asm volatile("cp.async.cg.shared.global [%0], [%1], 16;\n"
                 :: "r"(saddr), "l"(gptr));
}
__device__ __forceinline__ void cp_commit() {
    asm volatile("cp.async.commit_group;\n");
}
template <int N>
__device__ __forceinline__ void cp_wait() {
    asm volatile("cp.async.wait_group %0;\n" :: "n"(N));
}

// ---------------------------------------------------------------------------
// Dist role: one block per (batch, 16-channel group); double-buffered
// cp.async tiles; per-edge partials reduced into g_sum via REDG atomics.
// ---------------------------------------------------------------------------
__device__ void dist_role(const float* __restrict__ emb,
                          const int*   __restrict__ tree, int id) {
    float* buf0 = dyn_smem;
    float* buf1 = dyn_smem + TCH * NND;
    const int b   = id / GQ;
    const int g   = id % GQ;
    const int tid = threadIdx.x;

    const float* base = emb + ((size_t)b * CCH + (size_t)g * CPB) * NND;
    uint32_t s0 = (uint32_t)__cvta_generic_to_shared(buf0);
    uint32_t s1 = (uint32_t)__cvta_generic_to_shared(buf1);
    const int WORDS = TCH * NND / 4;

    for (int i = tid; i < WORDS; i += NT)
        cp_async16(s0 + i * 16, base + i * 4);
    cp_commit();

    const int2* tr2 = (const int2*)(tree + (size_t)b * EED * 2);
    int2 ed[EPT];
    float acc[EPT];
#pragma unroll
    for (int k = 0; k < EPT; k++) {
        int e = tid + k * NT;
        ed[k]  = (e < EED) ? tr2[e] : make_int2(0, 0);
        acc[k] = 0.f;
    }

    for (int t = 0; t < NSTEP; t++) {
        if (t + 1 < NSTEP) {
            uint32_t dst = (t & 1) ? s0 : s1;
            const float* srcp = base + (size_t)(t + 1) * TCH * NND;
            for (int i = tid; i < WORDS; i += NT)
                cp_async16(dst + i * 16, srcp + i * 4);
            cp_commit();
            cp_wait<1>();
        } else {
            cp_wait<0>();
        }
        __syncthreads();
        const float* cur = (t & 1) ? buf1 : buf0;
#pragma unroll
        for (int k = 0; k < EPT; k++) {
            float a0 = cur[ed[k].x];
            float b0 = cur[ed[k].y];
            float a1 = cur[NND + ed[k].x];
            float b1 = cur[NND + ed[k].y];
            float d0 = a0 - b0, d1 = a1 - b1;
            acc[k] += d0 * d0 + d1 * d1;
        }
        __syncthreads();
    }

    float* sp = g_sum + (size_t)b * EED;
#pragma unroll
    for (int k = 0; k < EPT; k++) {
        int e = tid + k * NT;
        if (e < EED) atomicAdd(sp + e, acc[k]);
    }
}

// ---------------------------------------------------------------------------
// Prologue role: tree-only. Depth via chunked parent walk, counting sort of
// edges by child depth; writes level-sorted (s,t), level offsets, meta.
// Runs concurrently with dist (no data dependency).
// ---------------------------------------------------------------------------
__device__ void prologue_role(const int* __restrict__ tree, int b) {
    const int tid = threadIdx.x;
    const int wid = tid >> 5;
    const int lid = tid & 31;

    int* par = (int*)dyn_smem;
    int* dep = par + NND;

    __shared__ int hist[MAXD + 1];
    __shared__ int lvlo[MAXD + 2];
    __shared__ int warpsum[16];
    __shared__ int s_maxLvl, s_bad;

    const int2* tr2 = (const int2*)(tree + (size_t)b * EED * 2);

    if (tid == 0) { s_maxLvl = 1; s_bad = 0; par[0] = 0; dep[0] = 0; }
    int2 ed[EPT];
#pragma unroll
    for (int k = 0; k < EPT; k++) {
        int e = tid + k * NT;
        ed[k] = (e < EED) ? tr2[e] : make_int2(0, 0);
        if (e < EED) par[ed[k].y] = ed[k].x;
    }
    __syncthreads();

#pragma unroll 1
    for (int c = 0; c < NCHUNK; c++) {
        int i = c * NT + tid;
        if (i > 0) {
            int B = c * NT;
            int j = par[i], d = 1;
            while (j >= B && j > 0) { j = par[j]; d++; }
            dep[i] = d + dep[j];
        }
        __syncthreads();
    }

    for (int k = tid; k <= MAXD; k += NT) hist[k] = 0;
    __syncthreads();
    int myd[EPT];
#pragma unroll
    for (int k = 0; k < EPT; k++) {
        int e = tid + k * NT;
        if (e < EED) {
            int d = dep[ed[k].y];
            myd[k] = d > MAXD ? MAXD : d;
            atomicAdd(&hist[myd[k]], 1);
        } else myd[k] = 0;
    }
    __syncthreads();

    // 2-barrier block scan over 512 bins
    int binv = 0, incl = 0, bin = 0;
    if (wid < 16) {
        bin  = wid * 32 + lid;
        binv = hist[bin];
        int v = binv;
#pragma unroll
        for (int off = 1; off < 32; off <<= 1) {
            int t = __shfl_up_sync(0xffffffffu, v, off);
            if (lid >= off) v += t;
        }
        if (lid == 31) warpsum[wid] = v;
        incl = v;
    }
    __syncthreads();
    if (wid == 0 && lid < 16) {
        int v = warpsum[lid];
#pragma unroll
        for (int off = 1; off < 16; off <<= 1) {
            int t = __shfl_up_sync(0xffffu, v, off);
            if (lid >= off) v += t;
        }
        warpsum[lid] = v;
    }
    __syncthreads();
    if (wid < 16) {
        incl += wid ? warpsum[wid - 1] : 0;
        lvlo[bin + 1] = incl;
        hist[bin] = incl - binv;
        if (binv > 0)  atomicMax(&s_maxLvl, bin);
        if (binv > 32) atomicMax(&s_bad, bin);
    }
    if (tid == 0) lvlo[0] = 0;
    __syncthreads();

    // scatter level-sorted edges to global
    int2* stp = g_ST + (size_t)b * EEDP;
#pragma unroll
    for (int k = 0; k < EPT; k++) {
        int e = tid + k * NT;
        if (e < EED) {
            int pos = atomicAdd(&hist[myd[k]], 1);
            stp[pos] = ed[k];
        }
    }
    for (int k = tid; k <= MAXD + 1; k += NT) g_lvlo[b][k] = lvlo[k];
    if (tid == 0) g_meta[b] = make_int2(s_maxLvl, s_bad);
}

__global__ void __launch_bounds__(NT, 1)
fused_kernel(const float* __restrict__ emb, const int* __restrict__ tree) {
    if (blockIdx.x < BS * GQ) dist_role(emb, tree, blockIdx.x);
    else                      prologue_role(tree, blockIdx.x - BS * GQ);
}

// ---------------------------------------------------------------------------
// Pass kernel: 16 blocks = (batch, field). Field 0 = F (init feature),
// field 1 = G (init ones). Weights from g_sum inline (edge id = t-1).
// smem: S float[NND] | ST int2[EEDP] | W float[EEDP]  (~147 KB)
// ---------------------------------------------------------------------------
__global__ void __launch_bounds__(NT, 1)
pass_kernel(const float* __restrict__ fin) {
    const int b     = blockIdx.x >> 1;
    const int which = blockIdx.x & 1;
    const int tid   = threadIdx.x;
    const int wid   = tid >> 5;
    const int lid   = tid & 31;

    char*  smbase = (char*)dyn_smem;
    float* S  = (float*)smbase;
    int2*  ST = (int2*)(smbase + (size_t)NND * 4);
    float* W  = (float*)(smbase + (size_t)NND * 4 + (size_t)EEDP * 8);

    __shared__ int lvlo[MAXD + 2];

    const int2 meta = g_meta[b];
    const int maxLvl = meta.x, bad = meta.y;

    for (int k = tid; k <= maxLvl + 1; k += NT) lvlo[k] = g_lvlo[b][k];

    // load sorted edges + compute weights (edge id = child - 1)
    const int2*  stp = g_ST + (size_t)b * EEDP;
    const float* sp  = g_sum + (size_t)b * EED;
    for (int i = tid; i < EED; i += NT) {
        int2 st = stp[i];
        ST[i] = st;
        W[i]  = __expf(-ZETA * __ldg(sp + (st.y - 1)));
    }

    // init field
    if (which == 0) {
        const float* fb = fin + (size_t)b * NND;
        for (int i = tid; i < NND; i += NT) S[i] = fb[i];
    } else {
        for (int i = tid; i < NND; i += NT) S[i] = 1.f;
    }
    __syncthreads();

    // ---- UP pass ----
    if (wid == 0) {
#pragma unroll 1
        for (int d = maxLvl; d > bad; --d) {
            int idx = lvlo[d] + lid;
            if (idx < lvlo[d + 1]) {
                int2 st = ST[idx];
                atomicAdd(&S[st.x], W[idx] * S[st.y]);
            }
            __syncwarp();
        }
    }
    __syncthreads();
#pragma unroll 1
    for (int d = bad; d >= 1; --d) {
        int end = lvlo[d + 1];
        for (int idx = lvlo[d] + tid; idx < end; idx += NT) {
            int2 st = ST[idx];
            atomicAdd(&S[st.x], W[idx] * S[st.y]);
        }
        __syncthreads();
    }

    // ---- DOWN pass ----
#pragma unroll 1
    for (int d = 1; d <= bad; ++d) {
        int end = lvlo[d + 1];
        for (int idx = lvlo[d] + tid; idx < end; idx += NT) {
            int2 st = ST[idx];
            float w = W[idx];
            S[st.y] = w * S[st.x] + (1.f - w * w) * S[st.y];
        }
        __syncthreads();
    }
    if (wid == 0) {
#pragma unroll 1
        for (int d = bad + 1; d <= maxLvl; ++d) {
            int idx = lvlo[d] + lid;
            if (idx < lvlo[d + 1]) {
                int2 st = ST[idx];
                float w = W[idx];
                S[st.y] = w * S[st.x] + (1.f - w * w) * S[st.y];
            }
            __syncwarp();
        }
    }
    __syncthreads();

    float* op = g_FZ[which] + (size_t)b * NND;
    for (int i = tid; i < NND; i += NT) op[i] = S[i];
}

// ---------------------------------------------------------------------------
// Divide kernel: out = F/G; also re-zeroes g_sum for the next replay.
// ---------------------------------------------------------------------------
__global__ void divide_kernel(float* __restrict__ out) {
    int idx = blockIdx.x * blockDim.x + threadIdx.x;
    if (idx < BS * NND)
        out[idx] = g_FZ[0][idx] / g_FZ[1][idx];
    if (idx < BS * EED)
        g_sum[idx] = 0.f;
}

// ---------------------------------------------------------------------------
extern "C" void kernel_launch(void* const* d_in, const int* in_sizes, int n_in,
                              void* d_out, int out_size) {
    const float* f    = (const float*)d_in[0];   // feature_in [8,1,96,96]
    const float* emb  = (const float*)d_in[1];   // embed_in   [8,256,96,96]
    const int*   tree = (const int*)d_in[2];     // tree       [8,9215,2]
    float*       out  = (float*)d_out;           // [8,1,96,96]

    size_t smem1 = 2 * (size_t)TCH * NND * sizeof(float);   // 147456 B
    cudaFuncSetAttribute(fused_kernel,
                         cudaFuncAttributeMaxDynamicSharedMemorySize,
                         (int)smem1);
    fused_kernel<<<GRID1, NT, smem1>>>(emb, tree);

    size_t smem2 = (size_t)NND * 4 + (size_t)EEDP * 8 + (size_t)EEDP * 4;
    cudaFuncSetAttribute(pass_kernel,
                         cudaFuncAttributeMaxDynamicSharedMemorySize,
                         (int)smem2);
    pass_kernel<<<2 * BS, NT, smem2>>>(f);

    divide_kernel<<<(BS * NND + 255) / 256, 256>>>(out);
}